// round 2
// baseline (speedup 1.0000x reference)
#include <cuda_runtime.h>
#include <cuda_bf16.h>
#include <math.h>
#include <stdint.h>

// Problem constants (fixed by setup_inputs)
#define ND 12288   // D
#define NH 1024    // HASH
#define NU 32      // units
#define NK 128     // BASIS
#define NB 16      // batch
#define NDEPTH 16

// ---------------- device scratch (no allocations allowed) ----------------
__device__ float g_xf[2 * NB * ND];           // ping-pong xf
__device__ float g_part[3 * NB * ND];         // big-GEMM split-K partials
__device__ float g_hpart[16 * NB * NH];       // hash split-K partials
__device__ float g_h[NB * NH];                // current hash
__device__ float g_gram[NU * NK * NK];        // per-unit Gram B^T B
__device__ float g_coeffp[4 * NU * NB * NK];  // coeff partials [fc][u][b][k]
__device__ float g_coeff[NB * NU * NK];       // summed coeff [b][u][k]
__device__ float g_mags[NB * NU];             // |proj|^2
__device__ int   g_route[NB];
__device__ int   g_routeh[NB * NDEPTH];

// ---------------- f32x2 helpers ----------------
__device__ __forceinline__ unsigned long long pk2(float lo, float hi) {
    unsigned long long r;
    asm("mov.b64 %0, {%1, %2};" : "=l"(r) : "f"(lo), "f"(hi));
    return r;
}
__device__ __forceinline__ void upk2(unsigned long long v, float& lo, float& hi) {
    asm("mov.b64 {%0, %1}, %2;" : "=f"(lo), "=f"(hi) : "l"(v));
}
__device__ __forceinline__ unsigned long long f2fma(unsigned long long a,
                                                    unsigned long long b,
                                                    unsigned long long c) {
    unsigned long long d;
    asm("fma.rn.f32x2 %0, %1, %2, %3;" : "=l"(d) : "l"(a), "l"(b), "l"(c));
    return d;
}

// ---------------- zero the hash-accumulator region of d_out ----------------
__global__ void k_init(float* __restrict__ out) {
    int i = blockIdx.x * 256 + threadIdx.x;
    if (i < NB * NH) out[i] = 0.0f;
}

// ---------------- Gram: G[u] = basis[u]^T basis[u] (128x128 per unit) ----------------
// grid (32, 4): u, 32-row i-chunk. 128 threads = j.
__global__ void __launch_bounds__(128) k_gram(const float* __restrict__ basis) {
    int u = blockIdx.x;
    int ic = blockIdx.y;            // i base = ic*32
    int tid = threadIdx.x;
    __shared__ float rows[8][128];
    unsigned long long acc[16];
    #pragma unroll
    for (int p = 0; p < 16; p++) acc[p] = 0ull;

    for (int fb = 0; fb < 128; fb++) {          // 128 stages of 8 f-rows
        __syncthreads();
        #pragma unroll
        for (int rr = 0; rr < 8; rr++)
            rows[rr][tid] = __ldg(basis + ((size_t)u * NH + fb * 8 + rr) * NK + tid);
        __syncthreads();
        #pragma unroll
        for (int rr = 0; rr < 8; rr++) {
            float bj = rows[rr][tid];
            unsigned long long wp = pk2(bj, bj);
            const ulonglong2* ip = (const ulonglong2*)&rows[rr][ic * 32];
            #pragma unroll
            for (int q = 0; q < 8; q++) {
                ulonglong2 v = ip[q];
                acc[2 * q + 0] = f2fma(v.x, wp, acc[2 * q + 0]);
                acc[2 * q + 1] = f2fma(v.y, wp, acc[2 * q + 1]);
            }
        }
    }
    #pragma unroll
    for (int p = 0; p < 16; p++) {
        float lo, hi;
        upk2(acc[p], lo, hi);
        g_gram[((size_t)u * NK + ic * 32 + 2 * p + 0) * NK + tid] = lo;
        g_gram[((size_t)u * NK + ic * 32 + 2 * p + 1) * NK + tid] = hi;
    }
}

// ---------------- generic split-K GEMM partial ----------------
// out[ksplit][b][col] = sum_{k in chunk} X[b][k] * W[k][col]
// grid (N/128, nsplit). 128 threads; each thread: 1 col x 16 batch (8 f32x2 accs).
template <bool STREAM>
__global__ void __launch_bounds__(128, 2)
k_gemm_part(const float* __restrict__ X, const float* __restrict__ W,
            int N, int klen, float* __restrict__ out) {
    __shared__ float xs[256][16];
    int tid = threadIdx.x;
    int col = blockIdx.x * 128 + tid;
    int k0 = blockIdx.y * klen;

    unsigned long long acc[8];
    #pragma unroll
    for (int i = 0; i < 8; i++) acc[i] = 0ull;

    for (int kc = 0; kc < klen; kc += 256) {
        __syncthreads();
        #pragma unroll
        for (int it = 0; it < 8; it++) {
            int idx = tid + it * 128;        // 0..1023 float4-units
            int b = idx & 15;
            int kq = idx >> 4;               // 0..63
            float4 v = *(const float4*)(X + (size_t)b * ND + k0 + kc + kq * 4);
            xs[kq * 4 + 0][b] = v.x;
            xs[kq * 4 + 1][b] = v.y;
            xs[kq * 4 + 2][b] = v.z;
            xs[kq * 4 + 3][b] = v.w;
        }
        __syncthreads();
        const float* Wp = W + (size_t)(k0 + kc) * N + col;
        #pragma unroll 16
        for (int k = 0; k < 256; k++) {
            float w = STREAM ? __ldcs(Wp + (size_t)k * N) : __ldg(Wp + (size_t)k * N);
            unsigned long long wp = pk2(w, w);
            const ulonglong2* xr = (const ulonglong2*)&xs[k][0];
            ulonglong2 q0 = xr[0], q1 = xr[1], q2 = xr[2], q3 = xr[3];
            acc[0] = f2fma(q0.x, wp, acc[0]);
            acc[1] = f2fma(q0.y, wp, acc[1]);
            acc[2] = f2fma(q1.x, wp, acc[2]);
            acc[3] = f2fma(q1.y, wp, acc[3]);
            acc[4] = f2fma(q2.x, wp, acc[4]);
            acc[5] = f2fma(q2.y, wp, acc[5]);
            acc[6] = f2fma(q3.x, wp, acc[6]);
            acc[7] = f2fma(q3.y, wp, acc[7]);
        }
    }
    float* op = out + (size_t)blockIdx.y * (NB * (size_t)N) + col;
    #pragma unroll
    for (int p = 0; p < 8; p++) {
        float lo, hi;
        upk2(acc[p], lo, hi);
        op[(size_t)(2 * p + 0) * N] = lo;
        op[(size_t)(2 * p + 1) * N] = hi;
    }
}

// ---------------- reduce 3 split-K partials + bias[route] + tanh -> xf_next ----------------
__global__ void k_reduce_tanh(const float* __restrict__ bias, float* __restrict__ Xout) {
    int idx = blockIdx.x * 256 + threadIdx.x;      // float4 index, 49152 total
    int b = idx / 3072;
    int j = (idx - b * 3072) * 4;
    size_t o = (size_t)b * ND + j;
    float4 s0 = *(const float4*)(g_part + o);
    float4 s1 = *(const float4*)(g_part + (size_t)NB * ND + o);
    float4 s2 = *(const float4*)(g_part + 2 * (size_t)NB * ND + o);
    int r = g_route[b];
    float4 bv = *(const float4*)(bias + (size_t)r * ND + j);
    float4 res;
    res.x = tanhf(s0.x + s1.x + s2.x + bv.x);
    res.y = tanhf(s0.y + s1.y + s2.y + bv.y);
    res.z = tanhf(s0.z + s1.z + s2.z + bv.z);
    res.w = tanhf(s0.w + s1.w + s2.w + bv.w);
    *(float4*)(Xout + o) = res;
}

// ---------------- reduce 16 hash partials -> g_h ----------------
__global__ void k_hreduce() {
    int i = blockIdx.x * 256 + threadIdx.x;     // 0..16383
    float s = 0.f;
    #pragma unroll
    for (int p = 0; p < 16; p++) s += g_hpart[(size_t)p * (NB * NH) + i];
    g_h[i] = s;
}

// ---------------- coeff partial: coeffp[fc][u][b][k] = sum_{f chunk} h[b][f]*basis[u][f][k] ----------------
// grid (32, 4): u, f-chunk of 256. 128 threads = k.
__global__ void __launch_bounds__(128) k_coeff(const float* __restrict__ basis) {
    int u = blockIdx.x;
    int fc = blockIdx.y;
    int tid = threadIdx.x;
    __shared__ float hs[256][16];
    #pragma unroll
    for (int it = 0; it < 32; it++) {
        int idx = tid + it * 128;
        int b = idx & 15;
        int f = idx >> 4;
        hs[f][b] = g_h[b * NH + fc * 256 + f];
    }
    __syncthreads();

    unsigned long long acc[8];
    #pragma unroll
    for (int i = 0; i < 8; i++) acc[i] = 0ull;

    const float* bp = basis + ((size_t)u * NH + fc * 256) * NK + tid;
    #pragma unroll 16
    for (int f = 0; f < 256; f++) {
        float bv = __ldg(bp + (size_t)f * NK);
        unsigned long long wp = pk2(bv, bv);
        const ulonglong2* xr = (const ulonglong2*)&hs[f][0];
        ulonglong2 q0 = xr[0], q1 = xr[1], q2 = xr[2], q3 = xr[3];
        acc[0] = f2fma(q0.x, wp, acc[0]);
        acc[1] = f2fma(q0.y, wp, acc[1]);
        acc[2] = f2fma(q1.x, wp, acc[2]);
        acc[3] = f2fma(q1.y, wp, acc[3]);
        acc[4] = f2fma(q2.x, wp, acc[4]);
        acc[5] = f2fma(q2.y, wp, acc[5]);
        acc[6] = f2fma(q3.x, wp, acc[6]);
        acc[7] = f2fma(q3.y, wp, acc[7]);
    }
    #pragma unroll
    for (int p = 0; p < 8; p++) {
        float lo, hi;
        upk2(acc[p], lo, hi);
        g_coeffp[(((size_t)fc * NU + u) * NB + 2 * p + 0) * NK + tid] = lo;
        g_coeffp[(((size_t)fc * NU + u) * NB + 2 * p + 1) * NK + tid] = hi;
    }
}

// ---------------- mags: sum coeff partials, mags[b][u] = c^T G[u] c ----------------
// grid (16, 32): b, u. 128 threads = j.
__global__ void __launch_bounds__(128) k_mags() {
    int b = blockIdx.x;
    int u = blockIdx.y;
    int tid = threadIdx.x;
    __shared__ float cs[128];
    __shared__ float red[128];

    float c = 0.f;
    #pragma unroll
    for (int fc = 0; fc < 4; fc++)
        c += g_coeffp[(((size_t)fc * NU + u) * NB + b) * NK + tid];
    cs[tid] = c;
    g_coeff[((size_t)b * NU + u) * NK + tid] = c;
    __syncthreads();

    float v = 0.f;
    const float* gp = g_gram + (size_t)u * NK * NK + tid;
    #pragma unroll 8
    for (int i = 0; i < 128; i++) v += gp[(size_t)i * NK] * cs[i];
    red[tid] = v * cs[tid];
    __syncthreads();
    for (int off = 64; off > 0; off >>= 1) {
        if (tid < off) red[tid] += red[tid + off];
        __syncthreads();
    }
    if (tid == 0) g_mags[b * NU + u] = red[0];
}

// ---------------- masked argmax per exemplar; record route ----------------
__global__ void k_argmax(int step, float* __restrict__ routes_out) {
    int tid = threadIdx.x;
    int b = tid >> 5;
    int u = tid & 31;
    float m = g_mags[b * NU + u];
    for (int t = 0; t < step; t++)
        if (g_routeh[b * NDEPTH + t] == u) m = -INFINITY;
    int bi = u;
    #pragma unroll
    for (int off = 16; off > 0; off >>= 1) {
        float om = __shfl_down_sync(0xffffffffu, m, off);
        int oi = __shfl_down_sync(0xffffffffu, bi, off);
        if (om > m || (om == m && oi < bi)) { m = om; bi = oi; }
    }
    if (u == 0) {
        g_route[b] = bi;
        g_routeh[b * NDEPTH + step] = bi;
        if (routes_out) routes_out[b * NDEPTH + step] = (float)bi;
    }
}

// ---------------- residual: out[b][f] += h[b][f] - (basis[u] @ coeff[b][u])[f] ----------------
// grid (16, 8): b, f-chunk of 128. 128 threads = f.
__global__ void __launch_bounds__(128) k_resid(const float* __restrict__ basis,
                                               float* __restrict__ out) {
    int b = blockIdx.x;
    int fc = blockIdx.y;
    int tid = threadIdx.x;
    int f = fc * 128 + tid;
    __shared__ float cs[128];
    __shared__ int su;
    if (tid == 0) su = g_route[b];
    __syncthreads();
    int u = su;
    cs[tid] = g_coeff[((size_t)b * NU + u) * NK + tid];
    __syncthreads();

    float acc = 0.f;
    const float4* bp = (const float4*)(basis + ((size_t)u * NH + f) * NK);
    #pragma unroll 8
    for (int kq = 0; kq < 32; kq++) {
        float4 v = __ldg(bp + kq);
        acc += v.x * cs[kq * 4 + 0] + v.y * cs[kq * 4 + 1] +
               v.z * cs[kq * 4 + 2] + v.w * cs[kq * 4 + 3];
    }
    int o = b * NH + f;
    out[o] += g_h[o] - acc;
}

// ---------------- launch ----------------
extern "C" void kernel_launch(void* const* d_in, const int* in_sizes, int n_in,
                              void* d_out, int out_size) {
    (void)in_sizes; (void)n_in;
    const float* x     = (const float*)d_in[0];
    const float* P     = (const float*)d_in[1];
    const float* basis = (const float*)d_in[2];
    const float* Wt    = (const float*)d_in[3];
    const float* bias  = (const float*)d_in[4];
    float* out = (float*)d_out;
    float* routes_out = (out_size >= NB * NH + NB * NDEPTH) ? out + NB * NH : nullptr;

    float *p_xf = nullptr, *p_part = nullptr, *p_hpart = nullptr;
    cudaGetSymbolAddress((void**)&p_xf, g_xf);
    cudaGetSymbolAddress((void**)&p_part, g_part);
    cudaGetSymbolAddress((void**)&p_hpart, g_hpart);

    k_init<<<64, 256>>>(out);
    k_gram<<<dim3(32, 4), 128>>>(basis);

    // initial hash: h = x @ P   (split-K 16 x 768)
    k_gemm_part<false><<<dim3(8, 16), 128>>>(x, P, NH, 768, p_hpart);
    k_hreduce<<<64, 256>>>();

    for (int s = 0; s < NDEPTH; s++) {
        k_coeff<<<dim3(32, 4), 128>>>(basis);
        k_mags<<<dim3(16, 32), 128>>>();
        k_argmax<<<1, 512>>>(s, routes_out);
        k_resid<<<dim3(16, 8), 128>>>(basis, out);

        if (s < NDEPTH - 1) {
            const float* X = (s == 0) ? x : (p_xf + (size_t)((s - 1) & 1) * NB * ND);
            float* Xn = p_xf + (size_t)(s & 1) * NB * ND;
            // big transform GEMM: split-K 3 x 4096, 288 blocks
            k_gemm_part<true><<<dim3(96, 3), 128>>>(X, Wt, ND, 4096, p_part);
            k_reduce_tanh<<<192, 256>>>(bias, Xn);
            // re-hash
            k_gemm_part<false><<<dim3(8, 16), 128>>>(Xn, P, NH, 768, p_hpart);
            k_hreduce<<<64, 256>>>();
        }
    }
}

// round 3
// speedup vs baseline: 1.4810x; 1.4810x over previous
#include <cuda_runtime.h>
#include <cuda_bf16.h>
#include <math.h>
#include <stdint.h>

// Problem constants (fixed by setup_inputs)
#define ND 12288   // D
#define NH 1024    // HASH
#define NU 32      // units
#define NK 128     // BASIS
#define NB 16      // batch
#define NDEPTH 16

#define KS_BIG 24   // split-K for the D x D transform GEMM
#define KS_HASH 96  // split-K for the hash GEMM

// ---------------- device scratch (no allocations allowed) ----------------
__device__ float g_xf[2 * NB * ND];                 // ping-pong xf
__device__ float g_part[KS_BIG * NB * ND];          // big-GEMM split-K partials (18.9MB)
__device__ float g_hpart[KS_HASH * NB * NH];        // hash split-K partials (6.3MB)
__device__ float g_h[NB * NH];                      // current hash
__device__ float g_gram[NU * NK * NK];              // per-unit Gram B^T B
__device__ float g_coeffp[4 * NU * NB * NK];        // coeff partials [fc][u][b][k]
__device__ float g_coeff[NB * NU * NK];             // summed coeff [b][u][k]
__device__ float g_mags[NB * NU];                   // |proj|^2
__device__ int   g_route[NB];
__device__ int   g_routeh[NB * NDEPTH];

// ---------------- f32x2 helpers ----------------
__device__ __forceinline__ unsigned long long pk2(float lo, float hi) {
    unsigned long long r;
    asm("mov.b64 %0, {%1, %2};" : "=l"(r) : "f"(lo), "f"(hi));
    return r;
}
__device__ __forceinline__ void upk2(unsigned long long v, float& lo, float& hi) {
    asm("mov.b64 {%0, %1}, %2;" : "=f"(lo), "=f"(hi) : "l"(v));
}
__device__ __forceinline__ unsigned long long f2fma(unsigned long long a,
                                                    unsigned long long b,
                                                    unsigned long long c) {
    unsigned long long d;
    asm("fma.rn.f32x2 %0, %1, %2, %3;" : "=l"(d) : "l"(a), "l"(b), "l"(c));
    return d;
}

// ---------------- zero the hash-accumulator region of d_out ----------------
__global__ void k_init(float* __restrict__ out) {
    int i = blockIdx.x * 256 + threadIdx.x;
    if (i < NB * NH) out[i] = 0.0f;
}

// ---------------- Gram: G[u] = basis[u]^T basis[u] (128x128 per unit) ----------------
// grid (32, 4): u, 32-row i-chunk. 128 threads = j.
__global__ void __launch_bounds__(128) k_gram(const float* __restrict__ basis) {
    int u = blockIdx.x;
    int ic = blockIdx.y;            // i base = ic*32
    int tid = threadIdx.x;
    __shared__ float rows[8][128];
    unsigned long long acc[16];
    #pragma unroll
    for (int p = 0; p < 16; p++) acc[p] = 0ull;

    for (int fb = 0; fb < 128; fb++) {          // 128 stages of 8 f-rows
        __syncthreads();
        #pragma unroll
        for (int rr = 0; rr < 8; rr++)
            rows[rr][tid] = __ldg(basis + ((size_t)u * NH + fb * 8 + rr) * NK + tid);
        __syncthreads();
        #pragma unroll
        for (int rr = 0; rr < 8; rr++) {
            float bj = rows[rr][tid];
            unsigned long long wp = pk2(bj, bj);
            const ulonglong2* ip = (const ulonglong2*)&rows[rr][ic * 32];
            #pragma unroll
            for (int q = 0; q < 8; q++) {
                ulonglong2 v = ip[q];
                acc[2 * q + 0] = f2fma(v.x, wp, acc[2 * q + 0]);
                acc[2 * q + 1] = f2fma(v.y, wp, acc[2 * q + 1]);
            }
        }
    }
    #pragma unroll
    for (int p = 0; p < 16; p++) {
        float lo, hi;
        upk2(acc[p], lo, hi);
        g_gram[((size_t)u * NK + ic * 32 + 2 * p + 0) * NK + tid] = lo;
        g_gram[((size_t)u * NK + ic * 32 + 2 * p + 1) * NK + tid] = hi;
    }
}

// ---------------- split-K GEMM partial, 4 cols/thread (LDG.128 on W) ----------------
// out[ks][b][col] = sum_{k in chunk} X[b][k] * W[k][col]
// grid (N/(TPB*4), nsplit), TPB threads. klen must be a multiple of 128.
template <bool STREAM, int TPB>
__global__ void __launch_bounds__(TPB, 2)
k_gemm4(const float* __restrict__ X, const float* __restrict__ W,
        int N, int klen, float* __restrict__ out) {
    __shared__ float xs[128][16];      // 128 k-rows x 16 batch (8KB)
    int tid = threadIdx.x;
    int col = (blockIdx.x * TPB + tid) * 4;
    int k0 = blockIdx.y * klen;

    unsigned long long acc[32];        // [c(4)][p(8)]: batch pairs (2p,2p+1)
    #pragma unroll
    for (int i = 0; i < 32; i++) acc[i] = 0ull;

    for (int kc = 0; kc < klen; kc += 128) {
        __syncthreads();
        // stage X[.][k0+kc .. +128) transposed into xs[k][b]
        #pragma unroll
        for (int idx = tid; idx < 512; idx += TPB) {   // 512 float4 units
            int b = idx & 15;
            int kq = idx >> 4;                         // 0..31
            float4 v = *(const float4*)(X + (size_t)b * ND + k0 + kc + kq * 4);
            xs[kq * 4 + 0][b] = v.x;
            xs[kq * 4 + 1][b] = v.y;
            xs[kq * 4 + 2][b] = v.z;
            xs[kq * 4 + 3][b] = v.w;
        }
        __syncthreads();

        const float* Wp = W + (size_t)(k0 + kc) * N + col;
        #pragma unroll 4
        for (int k = 0; k < 128; k++) {
            float4 w = STREAM ? __ldcs((const float4*)Wp)
                              : __ldg((const float4*)Wp);
            Wp += N;
            unsigned long long wx = pk2(w.x, w.x);
            unsigned long long wy = pk2(w.y, w.y);
            unsigned long long wz = pk2(w.z, w.z);
            unsigned long long ww = pk2(w.w, w.w);
            const ulonglong2* xr = (const ulonglong2*)&xs[k][0];
            ulonglong2 q0 = xr[0], q1 = xr[1], q2 = xr[2], q3 = xr[3];
            unsigned long long xp[8] = {q0.x, q0.y, q1.x, q1.y,
                                        q2.x, q2.y, q3.x, q3.y};
            #pragma unroll
            for (int p = 0; p < 8; p++) {
                acc[0 * 8 + p] = f2fma(xp[p], wx, acc[0 * 8 + p]);
                acc[1 * 8 + p] = f2fma(xp[p], wy, acc[1 * 8 + p]);
                acc[2 * 8 + p] = f2fma(xp[p], wz, acc[2 * 8 + p]);
                acc[3 * 8 + p] = f2fma(xp[p], ww, acc[3 * 8 + p]);
            }
        }
    }

    float* op = out + (size_t)blockIdx.y * (NB * (size_t)N) + col;
    #pragma unroll
    for (int p = 0; p < 8; p++) {
        float4 r0, r1;
        upk2(acc[0 * 8 + p], r0.x, r1.x);
        upk2(acc[1 * 8 + p], r0.y, r1.y);
        upk2(acc[2 * 8 + p], r0.z, r1.z);
        upk2(acc[3 * 8 + p], r0.w, r1.w);
        *(float4*)(op + (size_t)(2 * p + 0) * N) = r0;
        *(float4*)(op + (size_t)(2 * p + 1) * N) = r1;
    }
}

// ---------------- reduce KS_BIG split-K partials + bias[route] + tanh -> xf_next ----------------
__global__ void k_reduce_tanh(const float* __restrict__ bias, float* __restrict__ Xout) {
    int idx = blockIdx.x * 256 + threadIdx.x;      // float4 index, 49152 total
    int b = idx / 3072;
    int j = (idx - b * 3072) * 4;
    size_t o = (size_t)b * ND + j;
    float4 s = make_float4(0.f, 0.f, 0.f, 0.f);
    #pragma unroll
    for (int t = 0; t < KS_BIG; t++) {
        float4 v = *(const float4*)(g_part + (size_t)t * (NB * ND) + o);
        s.x += v.x; s.y += v.y; s.z += v.z; s.w += v.w;
    }
    int r = g_route[b];
    float4 bv = *(const float4*)(bias + (size_t)r * ND + j);
    float4 res;
    res.x = tanhf(s.x + bv.x);
    res.y = tanhf(s.y + bv.y);
    res.z = tanhf(s.z + bv.z);
    res.w = tanhf(s.w + bv.w);
    *(float4*)(Xout + o) = res;
}

// ---------------- reduce KS_HASH hash partials -> g_h ----------------
__global__ void k_hreduce() {
    int i = blockIdx.x * 256 + threadIdx.x;     // 0..16383
    float s = 0.f;
    #pragma unroll
    for (int p = 0; p < KS_HASH; p++) s += g_hpart[(size_t)p * (NB * NH) + i];
    g_h[i] = s;
}

// ---------------- coeff partial: coeffp[fc][u][b][k] = sum_{f chunk} h[b][f]*basis[u][f][k] ----------------
// grid (32, 4): u, f-chunk of 256. 128 threads = k.
__global__ void __launch_bounds__(128) k_coeff(const float* __restrict__ basis) {
    int u = blockIdx.x;
    int fc = blockIdx.y;
    int tid = threadIdx.x;
    __shared__ float hs[256][16];
    #pragma unroll
    for (int it = 0; it < 32; it++) {
        int idx = tid + it * 128;
        int b = idx & 15;
        int f = idx >> 4;
        hs[f][b] = g_h[b * NH + fc * 256 + f];
    }
    __syncthreads();

    unsigned long long acc[8];
    #pragma unroll
    for (int i = 0; i < 8; i++) acc[i] = 0ull;

    const float* bp = basis + ((size_t)u * NH + fc * 256) * NK + tid;
    #pragma unroll 16
    for (int f = 0; f < 256; f++) {
        float bv = __ldg(bp + (size_t)f * NK);
        unsigned long long wp = pk2(bv, bv);
        const ulonglong2* xr = (const ulonglong2*)&hs[f][0];
        ulonglong2 q0 = xr[0], q1 = xr[1], q2 = xr[2], q3 = xr[3];
        acc[0] = f2fma(q0.x, wp, acc[0]);
        acc[1] = f2fma(q0.y, wp, acc[1]);
        acc[2] = f2fma(q1.x, wp, acc[2]);
        acc[3] = f2fma(q1.y, wp, acc[3]);
        acc[4] = f2fma(q2.x, wp, acc[4]);
        acc[5] = f2fma(q2.y, wp, acc[5]);
        acc[6] = f2fma(q3.x, wp, acc[6]);
        acc[7] = f2fma(q3.y, wp, acc[7]);
    }
    #pragma unroll
    for (int p = 0; p < 8; p++) {
        float lo, hi;
        upk2(acc[p], lo, hi);
        g_coeffp[(((size_t)fc * NU + u) * NB + 2 * p + 0) * NK + tid] = lo;
        g_coeffp[(((size_t)fc * NU + u) * NB + 2 * p + 1) * NK + tid] = hi;
    }
}

// ---------------- mags: sum coeff partials, mags[b][u] = c^T G[u] c ----------------
// grid (16, 32): b, u. 128 threads = j.
__global__ void __launch_bounds__(128) k_mags() {
    int b = blockIdx.x;
    int u = blockIdx.y;
    int tid = threadIdx.x;
    __shared__ float cs[128];
    __shared__ float red[128];

    float c = 0.f;
    #pragma unroll
    for (int fc = 0; fc < 4; fc++)
        c += g_coeffp[(((size_t)fc * NU + u) * NB + b) * NK + tid];
    cs[tid] = c;
    g_coeff[((size_t)b * NU + u) * NK + tid] = c;
    __syncthreads();

    float v = 0.f;
    const float* gp = g_gram + (size_t)u * NK * NK + tid;
    #pragma unroll 8
    for (int i = 0; i < 128; i++) v += gp[(size_t)i * NK] * cs[i];
    red[tid] = v * cs[tid];
    __syncthreads();
    for (int off = 64; off > 0; off >>= 1) {
        if (tid < off) red[tid] += red[tid + off];
        __syncthreads();
    }
    if (tid == 0) g_mags[b * NU + u] = red[0];
}

// ---------------- masked argmax per exemplar; record route ----------------
__global__ void k_argmax(int step, float* __restrict__ routes_out) {
    int tid = threadIdx.x;
    int b = tid >> 5;
    int u = tid & 31;
    float m = g_mags[b * NU + u];
    for (int t = 0; t < step; t++)
        if (g_routeh[b * NDEPTH + t] == u) m = -INFINITY;
    int bi = u;
    #pragma unroll
    for (int off = 16; off > 0; off >>= 1) {
        float om = __shfl_down_sync(0xffffffffu, m, off);
        int oi = __shfl_down_sync(0xffffffffu, bi, off);
        if (om > m || (om == m && oi < bi)) { m = om; bi = oi; }
    }
    if (u == 0) {
        g_route[b] = bi;
        g_routeh[b * NDEPTH + step] = bi;
        if (routes_out) routes_out[b * NDEPTH + step] = (float)bi;
    }
}

// ---------------- residual: out[b][f] += h[b][f] - (basis[u] @ coeff[b][u])[f] ----------------
// grid (16, 8): b, f-chunk of 128. 128 threads = f.
__global__ void __launch_bounds__(128) k_resid(const float* __restrict__ basis,
                                               float* __restrict__ out) {
    int b = blockIdx.x;
    int fc = blockIdx.y;
    int tid = threadIdx.x;
    int f = fc * 128 + tid;
    __shared__ float cs[128];
    __shared__ int su;
    if (tid == 0) su = g_route[b];
    __syncthreads();
    int u = su;
    cs[tid] = g_coeff[((size_t)b * NU + u) * NK + tid];
    __syncthreads();

    float acc = 0.f;
    const float4* bp = (const float4*)(basis + ((size_t)u * NH + f) * NK);
    #pragma unroll 8
    for (int kq = 0; kq < 32; kq++) {
        float4 v = __ldg(bp + kq);
        acc += v.x * cs[kq * 4 + 0] + v.y * cs[kq * 4 + 1] +
               v.z * cs[kq * 4 + 2] + v.w * cs[kq * 4 + 3];
    }
    int o = b * NH + f;
    out[o] += g_h[o] - acc;
}

// ---------------- launch ----------------
extern "C" void kernel_launch(void* const* d_in, const int* in_sizes, int n_in,
                              void* d_out, int out_size) {
    (void)in_sizes; (void)n_in;
    const float* x     = (const float*)d_in[0];
    const float* P     = (const float*)d_in[1];
    const float* basis = (const float*)d_in[2];
    const float* Wt    = (const float*)d_in[3];
    const float* bias  = (const float*)d_in[4];
    float* out = (float*)d_out;
    float* routes_out = (out_size >= NB * NH + NB * NDEPTH) ? out + NB * NH : nullptr;

    float *p_xf = nullptr, *p_part = nullptr, *p_hpart = nullptr;
    cudaGetSymbolAddress((void**)&p_xf, g_xf);
    cudaGetSymbolAddress((void**)&p_part, g_part);
    cudaGetSymbolAddress((void**)&p_hpart, g_hpart);

    k_init<<<64, 256>>>(out);
    k_gram<<<dim3(32, 4), 128>>>(basis);

    // initial hash: h = x @ P   (split-K 96 x 128, 192 blocks)
    k_gemm4<false, 128><<<dim3(2, KS_HASH), 128>>>(x, P, NH, 128, p_hpart);
    k_hreduce<<<64, 256>>>();

    for (int s = 0; s < NDEPTH; s++) {
        k_coeff<<<dim3(32, 4), 128>>>(basis);
        k_mags<<<dim3(16, 32), 128>>>();
        k_argmax<<<1, 512>>>(s, routes_out);
        k_resid<<<dim3(16, 8), 128>>>(basis, out);

        if (s < NDEPTH - 1) {
            const float* X = (s == 0) ? x : (p_xf + (size_t)((s - 1) & 1) * NB * ND);
            float* Xn = p_xf + (size_t)(s & 1) * NB * ND;
            // big transform GEMM: split-K 24 x 512, grid (12,24)=288 blocks, 256 thr
            k_gemm4<true, 256><<<dim3(12, KS_BIG), 256>>>(X, Wt, ND, 512, p_part);
            k_reduce_tanh<<<192, 256>>>(bias, Xn);
            // re-hash
            k_gemm4<false, 128><<<dim3(2, KS_HASH), 128>>>(Xn, P, NH, 128, p_hpart);
            k_hreduce<<<64, 256>>>();
        }
    }
}

// round 4
// speedup vs baseline: 1.6417x; 1.1085x over previous
#include <cuda_runtime.h>
#include <cuda_bf16.h>
#include <math.h>
#include <stdint.h>

// Problem constants (fixed by setup_inputs)
#define ND 12288   // D
#define NH 1024    // HASH
#define NU 32      // units
#define NK 128     // BASIS
#define NB 16      // batch
#define NDEPTH 16

#define KS_BIG 24   // split-K for the D x D transform GEMM (grid 12x24=288 = 1 wave @2/SM)
#define KS_HASH 96  // split-K for the hash GEMM (grid 2x96=192 blocks)

// ---------------- device scratch (no allocations allowed) ----------------
__device__ float g_xf[2 * NB * ND];                 // ping-pong xf
__device__ float g_part[KS_BIG * NB * ND];          // big-GEMM split-K partials
__device__ float g_hpart[KS_HASH * NB * NH];        // hash split-K partials
__device__ float g_h[NB * NH];                      // current hash
__device__ float g_gram[NU * NK * NK];              // per-unit Gram B^T B
__device__ float g_coeffp[4 * NU * NB * NK];        // coeff partials [fc][u][b][k]
__device__ float g_coeff[NB * NU * NK];             // summed coeff [b][u][k]
__device__ float g_mags[NB * NU];                   // |proj|^2
__device__ int   g_route[NB];
__device__ int   g_routeh[NB * NDEPTH];

// ---------------- f32x2 helpers ----------------
__device__ __forceinline__ unsigned long long pk2(float lo, float hi) {
    unsigned long long r;
    asm("mov.b64 %0, {%1, %2};" : "=l"(r) : "f"(lo), "f"(hi));
    return r;
}
__device__ __forceinline__ void upk2(unsigned long long v, float& lo, float& hi) {
    asm("mov.b64 {%0, %1}, %2;" : "=f"(lo), "=f"(hi) : "l"(v));
}
__device__ __forceinline__ unsigned long long f2fma(unsigned long long a,
                                                    unsigned long long b,
                                                    unsigned long long c) {
    unsigned long long d;
    asm("fma.rn.f32x2 %0, %1, %2, %3;" : "=l"(d) : "l"(a), "l"(b), "l"(c));
    return d;
}

// ---------------- zero the hash-accumulator region of d_out ----------------
__global__ void k_init(float* __restrict__ out) {
    int i = blockIdx.x * 256 + threadIdx.x;
    if (i < NB * NH) out[i] = 0.0f;
}

// ---------------- Gram: G[u] = basis[u]^T basis[u] (128x128 per unit) ----------------
__global__ void __launch_bounds__(128) k_gram(const float* __restrict__ basis) {
    int u = blockIdx.x;
    int ic = blockIdx.y;
    int tid = threadIdx.x;
    __shared__ float rows[8][128];
    unsigned long long acc[16];
    #pragma unroll
    for (int p = 0; p < 16; p++) acc[p] = 0ull;

    for (int fb = 0; fb < 128; fb++) {
        __syncthreads();
        #pragma unroll
        for (int rr = 0; rr < 8; rr++)
            rows[rr][tid] = __ldg(basis + ((size_t)u * NH + fb * 8 + rr) * NK + tid);
        __syncthreads();
        #pragma unroll
        for (int rr = 0; rr < 8; rr++) {
            float bj = rows[rr][tid];
            unsigned long long wp = pk2(bj, bj);
            const ulonglong2* ip = (const ulonglong2*)&rows[rr][ic * 32];
            #pragma unroll
            for (int q = 0; q < 8; q++) {
                ulonglong2 v = ip[q];
                acc[2 * q + 0] = f2fma(v.x, wp, acc[2 * q + 0]);
                acc[2 * q + 1] = f2fma(v.y, wp, acc[2 * q + 1]);
            }
        }
    }
    #pragma unroll
    for (int p = 0; p < 16; p++) {
        float lo, hi;
        upk2(acc[p], lo, hi);
        g_gram[((size_t)u * NK + ic * 32 + 2 * p + 0) * NK + tid] = lo;
        g_gram[((size_t)u * NK + ic * 32 + 2 * p + 1) * NK + tid] = hi;
    }
}

// ---------------- split-K GEMM partial, 4 cols/thread, register-prefetch depth 4 ------
// out[ks][b][col] = sum_{k in chunk} X[b][k] * W[k][col]
// grid (N/(TPB*4), K/KLEN). Whole KLEN x 16 X-slice staged in smem once.
template <bool STREAM, int TPB, int KLEN, int MAXB>
__global__ void __launch_bounds__(TPB, MAXB)
k_gemm4(const float* __restrict__ X, const float* __restrict__ W,
        int N, float* __restrict__ out) {
    __shared__ float xs[KLEN][16];
    int tid = threadIdx.x;
    int col = (blockIdx.x * TPB + tid) * 4;
    int k0 = blockIdx.y * KLEN;

    // stage X[:, k0..k0+KLEN) transposed into xs[k][b]
    #pragma unroll
    for (int idx = tid; idx < KLEN * 4; idx += TPB) {   // float4 units
        int b = idx & 15;
        int kq = idx >> 4;
        float4 v = *(const float4*)(X + (size_t)b * ND + k0 + kq * 4);
        xs[kq * 4 + 0][b] = v.x;
        xs[kq * 4 + 1][b] = v.y;
        xs[kq * 4 + 2][b] = v.z;
        xs[kq * 4 + 3][b] = v.w;
    }

    unsigned long long acc[32];        // [c(4)][p(8)]: batch pairs (2p,2p+1)
    #pragma unroll
    for (int i = 0; i < 32; i++) acc[i] = 0ull;

    const float* Wp = W + (size_t)k0 * N + col;
    float4 wbuf[4];
    #pragma unroll
    for (int i = 0; i < 4; i++)
        wbuf[i] = STREAM ? __ldcs((const float4*)(Wp + (size_t)i * N))
                         : __ldg((const float4*)(Wp + (size_t)i * N));

    __syncthreads();

    #pragma unroll 4
    for (int k = 0; k < KLEN; k++) {
        float4 w = wbuf[k & 3];
        if (k + 4 < KLEN)
            wbuf[k & 3] = STREAM ? __ldcs((const float4*)(Wp + (size_t)(k + 4) * N))
                                 : __ldg((const float4*)(Wp + (size_t)(k + 4) * N));
        unsigned long long wx = pk2(w.x, w.x);
        unsigned long long wy = pk2(w.y, w.y);
        unsigned long long wz = pk2(w.z, w.z);
        unsigned long long ww = pk2(w.w, w.w);
        const ulonglong2* xr = (const ulonglong2*)&xs[k][0];
        ulonglong2 q0 = xr[0], q1 = xr[1], q2 = xr[2], q3 = xr[3];
        unsigned long long xp[8] = {q0.x, q0.y, q1.x, q1.y,
                                    q2.x, q2.y, q3.x, q3.y};
        #pragma unroll
        for (int p = 0; p < 8; p++) {
            acc[0 * 8 + p] = f2fma(xp[p], wx, acc[0 * 8 + p]);
            acc[1 * 8 + p] = f2fma(xp[p], wy, acc[1 * 8 + p]);
            acc[2 * 8 + p] = f2fma(xp[p], wz, acc[2 * 8 + p]);
            acc[3 * 8 + p] = f2fma(xp[p], ww, acc[3 * 8 + p]);
        }
    }

    float* op = out + (size_t)blockIdx.y * (NB * (size_t)N) + col;
    #pragma unroll
    for (int p = 0; p < 8; p++) {
        float4 r0, r1;
        upk2(acc[0 * 8 + p], r0.x, r1.x);
        upk2(acc[1 * 8 + p], r0.y, r1.y);
        upk2(acc[2 * 8 + p], r0.z, r1.z);
        upk2(acc[3 * 8 + p], r0.w, r1.w);
        *(float4*)(op + (size_t)(2 * p + 0) * N) = r0;
        *(float4*)(op + (size_t)(2 * p + 1) * N) = r1;
    }
}

// ---------------- reduce KS_BIG split-K partials + bias[route] + tanh -> xf_next ------
__global__ void k_reduce_tanh(const float* __restrict__ bias, float* __restrict__ Xout) {
    int idx = blockIdx.x * 256 + threadIdx.x;      // float4 index, 49152 total
    int b = idx / 3072;
    int j = (idx - b * 3072) * 4;
    size_t o = (size_t)b * ND + j;
    float4 s = make_float4(0.f, 0.f, 0.f, 0.f);
    #pragma unroll
    for (int t = 0; t < KS_BIG; t++) {
        float4 v = *(const float4*)(g_part + (size_t)t * (NB * ND) + o);
        s.x += v.x; s.y += v.y; s.z += v.z; s.w += v.w;
    }
    int r = g_route[b];
    float4 bv = *(const float4*)(bias + (size_t)r * ND + j);
    float4 res;
    res.x = tanhf(s.x + bv.x);
    res.y = tanhf(s.y + bv.y);
    res.z = tanhf(s.z + bv.z);
    res.w = tanhf(s.w + bv.w);
    *(float4*)(Xout + o) = res;
}

// ---------------- reduce KS_HASH hash partials -> g_h ----------------
__global__ void k_hreduce() {
    int i = blockIdx.x * 256 + threadIdx.x;     // 0..16383
    float s = 0.f;
    #pragma unroll
    for (int p = 0; p < KS_HASH; p++) s += g_hpart[(size_t)p * (NB * NH) + i];
    g_h[i] = s;
}

// ---------------- coeff partial: coeffp[fc][u][b][k] = sum_{f chunk} h[b][f]*basis[u][f][k] ----
__global__ void __launch_bounds__(128) k_coeff(const float* __restrict__ basis) {
    int u = blockIdx.x;
    int fc = blockIdx.y;
    int tid = threadIdx.x;
    __shared__ float hs[256][16];
    #pragma unroll
    for (int it = 0; it < 32; it++) {
        int idx = tid + it * 128;
        int b = idx & 15;
        int f = idx >> 4;
        hs[f][b] = g_h[b * NH + fc * 256 + f];
    }
    __syncthreads();

    unsigned long long acc[8];
    #pragma unroll
    for (int i = 0; i < 8; i++) acc[i] = 0ull;

    const float* bp = basis + ((size_t)u * NH + fc * 256) * NK + tid;
    #pragma unroll 16
    for (int f = 0; f < 256; f++) {
        float bv = __ldg(bp + (size_t)f * NK);
        unsigned long long wp = pk2(bv, bv);
        const ulonglong2* xr = (const ulonglong2*)&hs[f][0];
        ulonglong2 q0 = xr[0], q1 = xr[1], q2 = xr[2], q3 = xr[3];
        acc[0] = f2fma(q0.x, wp, acc[0]);
        acc[1] = f2fma(q0.y, wp, acc[1]);
        acc[2] = f2fma(q1.x, wp, acc[2]);
        acc[3] = f2fma(q1.y, wp, acc[3]);
        acc[4] = f2fma(q2.x, wp, acc[4]);
        acc[5] = f2fma(q2.y, wp, acc[5]);
        acc[6] = f2fma(q3.x, wp, acc[6]);
        acc[7] = f2fma(q3.y, wp, acc[7]);
    }
    #pragma unroll
    for (int p = 0; p < 8; p++) {
        float lo, hi;
        upk2(acc[p], lo, hi);
        g_coeffp[(((size_t)fc * NU + u) * NB + 2 * p + 0) * NK + tid] = lo;
        g_coeffp[(((size_t)fc * NU + u) * NB + 2 * p + 1) * NK + tid] = hi;
    }
}

// ---------------- mags: sum coeff partials, mags[b][u] = c^T G[u] c ----------------
__global__ void __launch_bounds__(128) k_mags() {
    int b = blockIdx.x;
    int u = blockIdx.y;
    int tid = threadIdx.x;
    __shared__ float cs[128];
    __shared__ float red[128];

    float c = 0.f;
    #pragma unroll
    for (int fc = 0; fc < 4; fc++)
        c += g_coeffp[(((size_t)fc * NU + u) * NB + b) * NK + tid];
    cs[tid] = c;
    g_coeff[((size_t)b * NU + u) * NK + tid] = c;
    __syncthreads();

    float v = 0.f;
    const float* gp = g_gram + (size_t)u * NK * NK + tid;
    #pragma unroll 8
    for (int i = 0; i < 128; i++) v += gp[(size_t)i * NK] * cs[i];
    red[tid] = v * cs[tid];
    __syncthreads();
    for (int off = 64; off > 0; off >>= 1) {
        if (tid < off) red[tid] += red[tid + off];
        __syncthreads();
    }
    if (tid == 0) g_mags[b * NU + u] = red[0];
}

// ---------------- masked argmax per exemplar; record route ----------------
__global__ void k_argmax(int step, float* __restrict__ routes_out) {
    int tid = threadIdx.x;
    int b = tid >> 5;
    int u = tid & 31;
    float m = g_mags[b * NU + u];
    for (int t = 0; t < step; t++)
        if (g_routeh[b * NDEPTH + t] == u) m = -INFINITY;
    int bi = u;
    #pragma unroll
    for (int off = 16; off > 0; off >>= 1) {
        float om = __shfl_down_sync(0xffffffffu, m, off);
        int oi = __shfl_down_sync(0xffffffffu, bi, off);
        if (om > m || (om == m && oi < bi)) { m = om; bi = oi; }
    }
    if (u == 0) {
        g_route[b] = bi;
        g_routeh[b * NDEPTH + step] = bi;
        if (routes_out) routes_out[b * NDEPTH + step] = (float)bi;
    }
}

// ---------------- residual: out[b][f] += h[b][f] - (basis[u] @ coeff[b][u])[f] ----------------
__global__ void __launch_bounds__(128) k_resid(const float* __restrict__ basis,
                                               float* __restrict__ out) {
    int b = blockIdx.x;
    int fc = blockIdx.y;
    int tid = threadIdx.x;
    int f = fc * 128 + tid;
    __shared__ float cs[128];
    __shared__ int su;
    if (tid == 0) su = g_route[b];
    __syncthreads();
    int u = su;
    cs[tid] = g_coeff[((size_t)b * NU + u) * NK + tid];
    __syncthreads();

    float acc = 0.f;
    const float4* bp = (const float4*)(basis + ((size_t)u * NH + f) * NK);
    #pragma unroll 8
    for (int kq = 0; kq < 32; kq++) {
        float4 v = __ldg(bp + kq);
        acc += v.x * cs[kq * 4 + 0] + v.y * cs[kq * 4 + 1] +
               v.z * cs[kq * 4 + 2] + v.w * cs[kq * 4 + 3];
    }
    int o = b * NH + f;
    out[o] += g_h[o] - acc;
}

// ---------------- launch ----------------
extern "C" void kernel_launch(void* const* d_in, const int* in_sizes, int n_in,
                              void* d_out, int out_size) {
    (void)in_sizes; (void)n_in;
    const float* x     = (const float*)d_in[0];
    const float* P     = (const float*)d_in[1];
    const float* basis = (const float*)d_in[2];
    const float* Wt    = (const float*)d_in[3];
    const float* bias  = (const float*)d_in[4];
    float* out = (float*)d_out;
    float* routes_out = (out_size >= NB * NH + NB * NDEPTH) ? out + NB * NH : nullptr;

    float *p_xf = nullptr, *p_part = nullptr, *p_hpart = nullptr;
    cudaGetSymbolAddress((void**)&p_xf, g_xf);
    cudaGetSymbolAddress((void**)&p_part, g_part);
    cudaGetSymbolAddress((void**)&p_hpart, g_hpart);

    k_init<<<64, 256>>>(out);
    k_gram<<<dim3(32, 4), 128>>>(basis);

    // initial hash: h = x @ P   (split-K 96 x 128)
    k_gemm4<false, 128, 128, 4><<<dim3(2, KS_HASH), 128>>>(x, P, NH, p_hpart);
    k_hreduce<<<64, 256>>>();

    for (int s = 0; s < NDEPTH; s++) {
        k_coeff<<<dim3(32, 4), 128>>>(basis);
        k_mags<<<dim3(16, 32), 128>>>();
        k_argmax<<<1, 512>>>(s, routes_out);
        k_resid<<<dim3(16, 8), 128>>>(basis, out);

        if (s < NDEPTH - 1) {
            const float* X = (s == 0) ? x : (p_xf + (size_t)((s - 1) & 1) * NB * ND);
            float* Xn = p_xf + (size_t)(s & 1) * NB * ND;
            // big transform GEMM: split-K 24 x 512, grid (12,24)=288 blocks, 256 thr
            k_gemm4<true, 256, 512, 2><<<dim3(12, KS_BIG), 256>>>(X, Wt, ND, p_part);
            k_reduce_tanh<<<192, 256>>>(bias, Xn);
            // re-hash
            k_gemm4<false, 128, 128, 4><<<dim3(2, KS_HASH), 128>>>(Xn, P, NH, p_hpart);
            k_hreduce<<<64, 256>>>();
        }
    }
}